// round 6
// baseline (speedup 1.0000x reference)
#include <cuda_runtime.h>

#define N_NODES 8
#define B_      4
#define C_      32
#define HW      9216           // 96*96
#define P_      64             // pixels per block tile
#define NT      (HW / P_)      // 144
#define TOTAL   (N_NODES * B_ * C_ * HW)

// smem: xs [8][32][64] = 16384 floats; ws [2 recv][2 set][32][32] = 4096 floats
#define XS_FLOATS 16384
#define WS_FLOATS 4096
#define SMEM_BYTES ((XS_FLOATS + WS_FLOATS) * 4)   // 81,920 B -> 2 blocks/SM

__device__ float g_buf0[TOTAL];
__device__ float g_buf1[TOTAL];
__device__ float g_wt[N_NODES * 2 * C_ * C_];   // [i][{wd,wc}][d][o]

__device__ __forceinline__ unsigned long long fma_f32x2(
    unsigned long long a, unsigned long long b, unsigned long long c) {
    unsigned long long d;
    asm("fma.rn.f32x2 %0, %1, %2, %3;" : "=l"(d) : "l"(a), "l"(b), "l"(c));
    return d;
}
union U2 { unsigned long long u; float2 f; };
__device__ __forceinline__ unsigned long long pack2(float lo, float hi) {
    U2 t; t.f.x = lo; t.f.y = hi; return t.u;
}

// ---- prep: transpose weights [i][o][2C] -> [i][{wd,wc=ws-wd}][d][o] ----
extern "C" __global__ void prep_kernel(const float* __restrict__ W_edge) {
    const int e = blockIdx.x * 256 + threadIdx.x;   // 0..8191 = i*1024 + d*32 + o
    const int o = e & 31;
    const int d = (e >> 5) & 31;
    const int i = e >> 10;
    const float wd = W_edge[(i * C_ + o) * (2 * C_) + d];
    const float ws = W_edge[(i * C_ + o) * (2 * C_) + C_ + d];
    g_wt[((i * 2 + 0) * C_ + d) * C_ + o] = wd;
    g_wt[((i * 2 + 1) * C_ + d) * C_ + o] = ws - wd;
}

// accY[m*2+p] = {y[o0+2m][px+p], y[o0+2m+1][px+p]}; stash x rows for epilogue
#define GEMM_BODY(WB, XR)                                                     \
  _Pragma("unroll")                                                           \
  for (int k = 0; k < 32; ++k) {                                              \
      const ulonglong2 wA = *(const ulonglong2*)((WB) + k * 32 + o0);         \
      const ulonglong2 wB = *(const ulonglong2*)((WB) + k * 32 + o0 + 4);     \
      const float2 xv = *(const float2*)((XR) + k * P_ + px);                 \
      if ((k >> 3) == wg) { sx[k & 7][0] = xv.x; sx[k & 7][1] = xv.y; }       \
      const unsigned long long x0 = pack2(xv.x, xv.x);                        \
      const unsigned long long x1 = pack2(xv.y, xv.y);                        \
      accY[0] = fma_f32x2(wA.x, x0, accY[0]);                                 \
      accY[1] = fma_f32x2(wA.x, x1, accY[1]);                                 \
      accY[2] = fma_f32x2(wA.y, x0, accY[2]);                                 \
      accY[3] = fma_f32x2(wA.y, x1, accY[3]);                                 \
      accY[4] = fma_f32x2(wB.x, x0, accY[4]);                                 \
      accY[5] = fma_f32x2(wB.x, x1, accY[5]);                                 \
      accY[6] = fma_f32x2(wB.y, x0, accY[6]);                                 \
      accY[7] = fma_f32x2(wB.y, x1, accY[7]);                                 \
  }

// out[i] = x_i + sum_{j!=i} relu(Wd_i @ x_j + C_i) * x_j,
// C_i = (Ws_i - Wd_i) @ x_i + b_i
extern "C" __global__ void __launch_bounds__(256, 2)
step_kernel(const float* __restrict__ in,
            const float* __restrict__ b_edge,   // [8][32]
            float* __restrict__ out)
{
    extern __shared__ float sm[];
    float* xs = sm;                 // [node][c][P_]
    float* ws = sm + XS_FLOATS;     // [h][{wd,wc}][d][o]

    const int bx    = blockIdx.x;
    const int b     = bx / NT;
    const int pbase = (bx % NT) * P_;
    const int tid   = threadIdx.x;

    // ---- x tile: 16384 floats = 4096 float4, 16/thread, coalesced ----
    #pragma unroll
    for (int t = 0; t < 16; ++t) {
        const int e   = tid + t * 256;     // 0..4095
        const int row = e >> 4;            // node*32 + c
        const int c4  = e & 15;
        const int node = row >> 5, c = row & 31;
        const float4 v = *reinterpret_cast<const float4*>(
            in + ((node * B_ + b) * C_ + c) * HW + pbase + c4 * 4);
        *reinterpret_cast<float4*>(xs + row * P_ + c4 * 4) = v;
    }

    const int h    = tid >> 7;             // half -> receiver parity
    const int wg   = (tid >> 5) & 3;       // o-group
    const int o0   = wg << 3;
    const int lane = tid & 31;
    const int px   = lane << 1;

    unsigned long long accY[8], accC[8];
    float accO[8][2];
    float sx[8][2];

    #pragma unroll 1
    for (int it = 0; it < 4; ++it) {
        const int i_n = (it << 1) + h;

        // ---- stage this iteration's weights (2 receivers x {wd,wc} = 16KB) ----
        __syncthreads();   // protect ws from previous iteration's readers
        {
            const float4* src = reinterpret_cast<const float4*>(
                g_wt + (it << 1) * (2 * C_ * C_));
            float4* dst = reinterpret_cast<float4*>(ws);
            #pragma unroll
            for (int t = 0; t < 4; ++t)
                dst[tid + t * 256] = src[tid + t * 256];
        }
        __syncthreads();

        const float* wdi = ws + (h * 2 + 0) * (C_ * C_);
        const float* wci = ws + (h * 2 + 1) * (C_ * C_);

        // ---- C-GEMM: C = Wc_i @ x_i + b_i (stashes x_i for residual) ----
        {
            const ulonglong2 b01 = __ldg(reinterpret_cast<const ulonglong2*>(
                b_edge + i_n * C_ + o0));
            const ulonglong2 b23 = __ldg(reinterpret_cast<const ulonglong2*>(
                b_edge + i_n * C_ + o0 + 4));
            accY[0] = b01.x; accY[1] = b01.x;
            accY[2] = b01.y; accY[3] = b01.y;
            accY[4] = b23.x; accY[5] = b23.x;
            accY[6] = b23.y; accY[7] = b23.y;
            const float* xrow = xs + i_n * (C_ * P_);
            GEMM_BODY(wci, xrow)
            #pragma unroll
            for (int q = 0; q < 8; ++q) accC[q] = accY[q];
            #pragma unroll
            for (int n = 0; n < 8; ++n) {
                accO[n][0] = sx[n][0]; accO[n][1] = sx[n][1];
            }
        }

        // ---- j-loop ----
        #pragma unroll 1
        for (int jl = 0; jl < 7; ++jl) {
            const int jj = jl + (jl >= i_n ? 1 : 0);
            #pragma unroll
            for (int q = 0; q < 8; ++q) accY[q] = accC[q];
            const float* xrow = xs + jj * (C_ * P_);
            GEMM_BODY(wdi, xrow)
            #pragma unroll
            for (int m = 0; m < 4; ++m) {
                #pragma unroll
                for (int p = 0; p < 2; ++p) {
                    U2 y; y.u = accY[m * 2 + p];
                    accO[2 * m + 0][p] = fmaf(fmaxf(y.f.x, 0.0f),
                                              sx[2 * m + 0][p], accO[2 * m + 0][p]);
                    accO[2 * m + 1][p] = fmaf(fmaxf(y.f.y, 0.0f),
                                              sx[2 * m + 1][p], accO[2 * m + 1][p]);
                }
            }
        }

        // ---- store: 8 channel rows x float2 (coalesced 256B/warp) ----
        #pragma unroll
        for (int n = 0; n < 8; ++n) {
            float2 v; v.x = accO[n][0]; v.y = accO[n][1];
            *reinterpret_cast<float2*>(
                out + ((i_n * B_ + b) * C_ + (o0 + n)) * HW + pbase + px) = v;
        }
    }
}

extern "C" void kernel_launch(void* const* d_in, const int* in_sizes, int n_in,
                              void* d_out, int out_size) {
    const float* nodes = (const float*)d_in[0];
    const float* W     = (const float*)d_in[1];
    const float* bvec  = (const float*)d_in[2];
    float* out         = (float*)d_out;

    float *buf0 = nullptr, *buf1 = nullptr;
    cudaGetSymbolAddress((void**)&buf0, g_buf0);
    cudaGetSymbolAddress((void**)&buf1, g_buf1);

    cudaFuncSetAttribute(step_kernel,
                         cudaFuncAttributeMaxDynamicSharedMemorySize, SMEM_BYTES);

    prep_kernel<<<32, 256>>>(W);                 // transpose weights once

    const dim3 grid(B_ * NT);   // 576 blocks = 2 waves @ 2 blocks/SM
    const dim3 block(256);
    step_kernel<<<grid, block, SMEM_BYTES>>>(nodes, bvec, buf0);
    step_kernel<<<grid, block, SMEM_BYTES>>>(buf0,  bvec, buf1);
    step_kernel<<<grid, block, SMEM_BYTES>>>(buf1,  bvec, out);
}